// round 2
// baseline (speedup 1.0000x reference)
#include <cuda_runtime.h>
#include <cuda_bf16.h>
#include <math.h>

// ---------------------------------------------------------------------------
// SecDecoder: outputs (flattened, concatenated in tuple order)
//   rp        [total]        = (M @ arange(ncol)) / ncol
//   gaps_start[nseq]         = sa[start_row]/ncol
//   gaps_in   [n_keep]       = (sa[g+1]-sa[g]-1)/ncol, g not a seq boundary
//   gaps_end  [nseq]         = (ncol - sa[end_row] - 1)/ncol
//   col_dist  [ncol*nout]    = softmax(columns @ W + b)
// ---------------------------------------------------------------------------

#define MAX_TOTAL 131072
#define MAX_NSEQ  1024

__device__ float      g_sa[MAX_TOTAL];   // soft_argmax scratch
__device__ long long  g_cs[MAX_NSEQ];    // cumsum(sequence_lengths)

// Dtype-agnostic sequence_lengths accessor. The harness may pass int64 (as in
// the reference) or downcast to int32. Lengths are strictly positive, so for
// a little-endian int64 buffer the second 32-bit word (high half of length 0)
// is 0, while for int32 it's the second length (nonzero). Probe reads only
// the first 8 bytes, in-bounds for both layouts.
__device__ __forceinline__ bool sl_is_int64(const void* sl) {
    const int* p = (const int*)sl;
    return p[1] == 0;
}
__device__ __forceinline__ long long sl_get(const void* sl, bool is64, int i) {
    if (is64) return ((const long long*)sl)[i];
    return (long long)((const int*)sl)[i];
}

// ---------------------------------------------------------------------------
// Kernel A: soft_argmax, one warp per row (1024 f32 = 8 float4 per lane).
// Pure HBM streaming — the roofline of this problem.
// ---------------------------------------------------------------------------
__global__ void __launch_bounds__(256) soft_argmax_kernel(
    const float* __restrict__ M, float* __restrict__ out_rp,
    int total, int ncol, float inv_ncol)
{
    int warp = (blockIdx.x * blockDim.x + threadIdx.x) >> 5;
    int lane = threadIdx.x & 31;
    if (warp >= total) return;

    const float4* row = reinterpret_cast<const float4*>(M) + (size_t)warp * (ncol >> 2);
    float sum = 0.f;
    int nvec = ncol >> 2;   // 256 for ncol=1024
#pragma unroll 8
    for (int k = lane; k < nvec; k += 32) {
        float4 v = __ldg(row + k);
        float c = (float)(k << 2);
        sum = fmaf(v.x, c,        sum);
        sum = fmaf(v.y, c + 1.0f, sum);
        sum = fmaf(v.z, c + 2.0f, sum);
        sum = fmaf(v.w, c + 3.0f, sum);
    }
#pragma unroll
    for (int o = 16; o; o >>= 1)
        sum += __shfl_down_sync(0xffffffffu, sum, o);

    if (lane == 0) {
        g_sa[warp]   = sum;
        out_rp[warp] = sum * inv_ncol;   // /1024 is exact (power of two)
    }
}

// ---------------------------------------------------------------------------
// Kernel B: cumsum of sequence_lengths (Hillis-Steele in smem, nseq<=512),
// then gaps_start / gaps_end. One block.
// ---------------------------------------------------------------------------
__global__ void boundaries_kernel(
    const void* __restrict__ sl, float* __restrict__ out,
    int nseq, int total, float ncolf, float inv_ncol, int off_gs, int off_ge)
{
    __shared__ long long s[MAX_NSEQ];
    int t = threadIdx.x;
    bool is64 = sl_is_int64(sl);
    for (int i = t; i < nseq; i += blockDim.x) s[i] = sl_get(sl, is64, i);
    __syncthreads();

    // inclusive scan (assumes nseq <= blockDim.x; nseq=500, blockDim=512)
    for (int d = 1; d < nseq; d <<= 1) {
        long long v = 0;
        if (t < nseq && t >= d) v = s[t - d];
        __syncthreads();
        if (t < nseq) s[t] += v;
        __syncthreads();
    }

    if (t < nseq) {
        long long cs_t = s[t];
        g_cs[t] = cs_t;
        long long row0 = (t == 0) ? 0 : s[t - 1];
        long long rowe = cs_t - 1;
        // clamp defensively (should always hold for valid inputs)
        if (row0 < 0) row0 = 0; if (row0 >= total) row0 = total - 1;
        if (rowe < 0) rowe = 0; if (rowe >= total) rowe = total - 1;
        out[off_gs + t] = g_sa[row0] * inv_ncol;
        out[off_ge + t] = (ncolf - g_sa[rowe] - 1.0f) * inv_ncol;
    }
}

// ---------------------------------------------------------------------------
// Kernel C: interior gaps with boundary-gap removal + compaction.
// Binary search over cumsum (cached in smem, 4/8KB) gives both the "is
// removed" test and the compacted output index.
// ---------------------------------------------------------------------------
__global__ void __launch_bounds__(256) gaps_in_kernel(
    float* __restrict__ out, int total, int nseq,
    float inv_ncol, int off_gin)
{
    __shared__ long long cs_s[MAX_NSEQ];
    for (int i = threadIdx.x; i < nseq; i += blockDim.x) cs_s[i] = g_cs[i];
    __syncthreads();

    int g = blockIdx.x * blockDim.x + threadIdx.x;
    if (g >= total - 1) return;

    // count of k in [0, nseq-2] with cs[k] <= g
    int lo = 0, hi = nseq - 1;            // exclusive upper over first nseq-1
    while (lo < hi) {
        int mid = (lo + hi) >> 1;
        if (cs_s[mid] <= (long long)g) lo = mid + 1; else hi = mid;
    }
    int cnt = lo;
    bool removed = (cnt < nseq - 1) && (cs_s[cnt] == (long long)g + 1);
    if (!removed) {
        float gap = g_sa[g + 1] - g_sa[g] - 1.0f;
        int idx = off_gin + (g - cnt);
        out[idx] = gap * inv_ncol;
    }
}

// ---------------------------------------------------------------------------
// Kernel D: col_dist = softmax(columns @ W + b).
// blockDim (32, 8): lane = output class o (26 active), y = row within block.
// columns reads broadcast across lanes; W reads coalesced across lanes.
// ---------------------------------------------------------------------------
__global__ void __launch_bounds__(256) coldist_kernel(
    const float* __restrict__ columns, const float* __restrict__ W,
    const float* __restrict__ b, float* __restrict__ out,
    int ncol, int dcol, int nout, int off_cd)
{
    int o = threadIdx.x;
    int r = blockIdx.x * blockDim.y + threadIdx.y;
    if (r >= ncol) return;

    const float* crow = columns + (size_t)r * dcol;
    bool active = (o < nout);
    float acc = active ? __ldg(b + o) : 0.f;

    int j = 0;
#pragma unroll 4
    for (; j + 4 <= dcol; j += 4) {
        float x0 = __ldg(crow + j);
        float x1 = __ldg(crow + j + 1);
        float x2 = __ldg(crow + j + 2);
        float x3 = __ldg(crow + j + 3);
        if (active) {
            acc = fmaf(x0, __ldg(W + (size_t)(j    ) * nout + o), acc);
            acc = fmaf(x1, __ldg(W + (size_t)(j + 1) * nout + o), acc);
            acc = fmaf(x2, __ldg(W + (size_t)(j + 2) * nout + o), acc);
            acc = fmaf(x3, __ldg(W + (size_t)(j + 3) * nout + o), acc);
        }
    }
    for (; j < dcol; j++) {
        float x = __ldg(crow + j);
        if (active) acc = fmaf(x, __ldg(W + (size_t)j * nout + o), acc);
    }

    // softmax across lanes 0..nout-1
    float val = active ? acc : -INFINITY;
    float m = val;
#pragma unroll
    for (int s = 16; s; s >>= 1) m = fmaxf(m, __shfl_xor_sync(0xffffffffu, m, s));
    float e = active ? expf(val - m) : 0.f;
    float sum = e;
#pragma unroll
    for (int s = 16; s; s >>= 1) sum += __shfl_xor_sync(0xffffffffu, sum, s);

    if (active) out[off_cd + (size_t)r * nout + o] = e / sum;
}

// ---------------------------------------------------------------------------
extern "C" void kernel_launch(void* const* d_in, const int* in_sizes, int n_in,
                              void* d_out, int out_size)
{
    const float* M    = (const float*)d_in[0];
    const float* cols = (const float*)d_in[1];
    const void*  sl   = d_in[2];            // int32 or int64, probed on device
    const float* W    = (const float*)d_in[3];
    const float* b    = (const float*)d_in[4];
    float*       out  = (float*)d_out;

    int nout = in_sizes[4];                 // 26
    int dcol = in_sizes[3] / nout;          // 512
    int ncol = in_sizes[1] / dcol;          // 1024
    int total = in_sizes[0] / ncol;         // 100000
    int nseq = in_sizes[2];                 // 500

    float ncolf = (float)ncol;
    float inv_ncol = 1.0f / ncolf;

    int n_keep = (total - 1) - (nseq - 1);
    int off_gs  = total;
    int off_gin = total + nseq;
    int off_ge  = off_gin + n_keep;
    int off_cd  = off_ge + nseq;

    // A: soft_argmax (HBM roofline kernel)
    {
        int warps_per_block = 256 / 32;
        int blocks = (total + warps_per_block - 1) / warps_per_block;
        soft_argmax_kernel<<<blocks, 256>>>(M, out, total, ncol, inv_ncol);
    }
    // B: cumsum + start/end gaps
    boundaries_kernel<<<1, 512>>>(sl, out, nseq, total, ncolf, inv_ncol, off_gs, off_ge);
    // C: interior gaps (compacted)
    {
        int n = total - 1;
        int blocks = (n + 255) / 256;
        gaps_in_kernel<<<blocks, 256>>>(out, total, nseq, inv_ncol, off_gin);
    }
    // D: col_dist softmax head
    {
        dim3 blk(32, 8);
        int blocks = (ncol + 7) / 8;
        coldist_kernel<<<blocks, blk>>>(cols, W, b, out, ncol, dcol, nout, off_cd);
    }
}

// round 3
// speedup vs baseline: 1.2956x; 1.2956x over previous
#include <cuda_runtime.h>
#include <cuda_bf16.h>
#include <math.h>

// ---------------------------------------------------------------------------
// SecDecoder outputs (flattened, concatenated in tuple order)
//   rp        [total]     = (M @ arange(ncol)) / ncol
//   gaps_start[nseq]      = sa[start_row]/ncol
//   gaps_in   [n_keep]    = (sa[g+1]-sa[g]-1)/ncol, g not a seq boundary
//   gaps_end  [nseq]      = (ncol - sa[end_row] - 1)/ncol
//   col_dist  [ncol*nout] = softmax(columns @ W + b)
// ---------------------------------------------------------------------------

#define MAX_TOTAL 131072
#define NOUT      26     // fixed by problem
#define JS        448    // j-range of W kept in smem (448*27*4 = 48384 B < 48KB)

__device__ float g_sa[MAX_TOTAL];   // soft_argmax scratch

// Dtype-agnostic sequence_lengths accessor (harness may pass int64 or int32).
// Lengths are strictly positive; little-endian int64 => word[1]==0.
__device__ __forceinline__ bool sl_is_int64(const void* sl) {
    return ((const int*)sl)[1] == 0;
}
__device__ __forceinline__ long long sl_get(const void* sl, bool is64, int i) {
    if (is64) return ((const long long*)sl)[i];
    return (long long)((const int*)sl)[i];
}

// ---------------------------------------------------------------------------
// Kernel A: soft_argmax, one warp per row (8 float4 per lane).
// Pure HBM streaming — the roofline of this problem. Do not disturb.
// ---------------------------------------------------------------------------
__global__ void __launch_bounds__(256) soft_argmax_kernel(
    const float* __restrict__ M, float* __restrict__ out_rp,
    int total, int ncol, float inv_ncol)
{
    int warp = (blockIdx.x * blockDim.x + threadIdx.x) >> 5;
    int lane = threadIdx.x & 31;
    if (warp >= total) return;

    const float4* row = reinterpret_cast<const float4*>(M) + (size_t)warp * (ncol >> 2);
    float sum = 0.f;
    int nvec = ncol >> 2;
#pragma unroll 8
    for (int k = lane; k < nvec; k += 32) {
        float4 v = __ldg(row + k);
        float c = (float)(k << 2);
        sum = fmaf(v.x, c,        sum);
        sum = fmaf(v.y, c + 1.0f, sum);
        sum = fmaf(v.z, c + 2.0f, sum);
        sum = fmaf(v.w, c + 3.0f, sum);
    }
#pragma unroll
    for (int o = 16; o; o >>= 1)
        sum += __shfl_down_sync(0xffffffffu, sum, o);

    if (lane == 0) {
        g_sa[warp]   = sum;
        out_rp[warp] = sum * inv_ncol;
    }
}

// ---------------------------------------------------------------------------
// Kernel BC: fused boundaries + interior gaps. Every block redundantly scans
// the 500 sequence lengths in smem (cheap: 9 Hillis-Steele rounds), block 0
// additionally writes gaps_start / gaps_end. Interior gaps use a binary
// search over the in-smem cumsum for the removal test + compaction index.
// ---------------------------------------------------------------------------
__global__ void __launch_bounds__(512) bc_kernel(
    const void* __restrict__ sl, float* __restrict__ out,
    int nseq, int total, float ncolf, float inv_ncol,
    int off_gs, int off_gin, int off_ge)
{
    __shared__ long long s[512];
    int t = threadIdx.x;
    bool is64 = sl_is_int64(sl);
    s[t] = (t < nseq) ? sl_get(sl, is64, t) : 0;
    __syncthreads();

    // inclusive scan over [0, nseq) (nseq <= 512)
    for (int d = 1; d < nseq; d <<= 1) {
        long long v = (t >= d) ? s[t - d] : 0;
        __syncthreads();
        s[t] += v;
        __syncthreads();
    }

    if (blockIdx.x == 0 && t < nseq) {
        long long cs_t = s[t];
        long long row0 = (t == 0) ? 0 : s[t - 1];
        long long rowe = cs_t - 1;
        if (row0 < 0) row0 = 0; if (row0 >= total) row0 = total - 1;
        if (rowe < 0) rowe = 0; if (rowe >= total) rowe = total - 1;
        out[off_gs + t] = g_sa[row0] * inv_ncol;
        out[off_ge + t] = (ncolf - g_sa[rowe] - 1.0f) * inv_ncol;
    }

    int g = blockIdx.x * blockDim.x + t;
    if (g >= total - 1) return;

    // count of k in [0, nseq-2] with cs[k] <= g
    int lo = 0, hi = nseq - 1;
    while (lo < hi) {
        int mid = (lo + hi) >> 1;
        if (s[mid] <= (long long)g) lo = mid + 1; else hi = mid;
    }
    int cnt = lo;
    bool removed = (cnt < nseq - 1) && (s[cnt] == (long long)g + 1);
    if (!removed) {
        float gap = g_sa[g + 1] - g_sa[g] - 1.0f;
        out[off_gin + (g - cnt)] = gap * inv_ncol;
    }
}

// ---------------------------------------------------------------------------
// Kernel D: col_dist = softmax(columns @ W + b).
// Warp per row, lanes split the j (dcol) dimension: coalesced x loads,
// 26 register accumulators, W tile in smem with stride-27 padding
// (gcd(27,32)=1 -> conflict-free LDS). j >= JS handled from global (W is
// L1-resident). Butterfly-reduce 26 sums, warp softmax across lanes 0..25.
// ---------------------------------------------------------------------------
__global__ void __launch_bounds__(256) coldist_kernel(
    const float* __restrict__ columns, const float* __restrict__ W,
    const float* __restrict__ b, float* __restrict__ out,
    int ncol, int dcol, int off_cd)
{
    __shared__ float Ws[JS * 27];   // 48384 bytes

    int tid  = threadIdx.x;
    int warp = tid >> 5;
    int lane = tid & 31;

    // cooperative load of W[0:JS][0:26] into padded smem
    for (int idx = tid; idx < JS * NOUT; idx += 256) {
        int j = idx / NOUT;
        int o = idx - j * NOUT;
        Ws[j * 27 + o] = W[idx];
    }
    __syncthreads();

    int r = blockIdx.x * 8 + warp;
    if (r >= ncol) return;

    const float* crow = columns + (size_t)r * dcol;

    float acc[NOUT];
#pragma unroll
    for (int o = 0; o < NOUT; o++) acc[o] = 0.f;

    int kmax = dcol >> 5;           // 16 for dcol=512
#pragma unroll 2
    for (int k = 0; k < kmax; k++) {
        int j = (k << 5) + lane;
        float x = crow[j];
        if (j < JS) {
            const float* wrow = &Ws[j * 27];
#pragma unroll
            for (int o = 0; o < NOUT; o++)
                acc[o] = fmaf(x, wrow[o], acc[o]);
        } else {
            const float* wrow = &W[(size_t)j * NOUT];
#pragma unroll
            for (int o = 0; o < NOUT; o++)
                acc[o] = fmaf(x, __ldg(wrow + o), acc[o]);
        }
    }

    // butterfly-reduce each accumulator across the warp
#pragma unroll
    for (int o = 0; o < NOUT; o++) {
#pragma unroll
        for (int sft = 16; sft; sft >>= 1)
            acc[o] += __shfl_xor_sync(0xffffffffu, acc[o], sft);
    }

    // lane o takes logit o (+ bias); softmax across lanes
    float val = -INFINITY;
#pragma unroll
    for (int o = 0; o < NOUT; o++)
        if (lane == o) val = acc[o];
    bool active = (lane < NOUT);
    if (active) val += __ldg(b + lane);
    else        val  = -INFINITY;

    float m = val;
#pragma unroll
    for (int sft = 16; sft; sft >>= 1)
        m = fmaxf(m, __shfl_xor_sync(0xffffffffu, m, sft));
    float e = active ? expf(val - m) : 0.f;
    float sum = e;
#pragma unroll
    for (int sft = 16; sft; sft >>= 1)
        sum += __shfl_xor_sync(0xffffffffu, sum, sft);

    if (active) out[off_cd + (size_t)r * NOUT + lane] = e / sum;
}

// ---------------------------------------------------------------------------
extern "C" void kernel_launch(void* const* d_in, const int* in_sizes, int n_in,
                              void* d_out, int out_size)
{
    const float* M    = (const float*)d_in[0];
    const float* cols = (const float*)d_in[1];
    const void*  sl   = d_in[2];            // int32 or int64, probed on device
    const float* W    = (const float*)d_in[3];
    const float* b    = (const float*)d_in[4];
    float*       out  = (float*)d_out;

    int nout  = in_sizes[4];                // 26
    int dcol  = in_sizes[3] / nout;         // 512
    int ncol  = in_sizes[1] / dcol;         // 1024
    int total = in_sizes[0] / ncol;         // 100000
    int nseq  = in_sizes[2];                // 500

    float ncolf    = (float)ncol;
    float inv_ncol = 1.0f / ncolf;

    int n_keep  = (total - 1) - (nseq - 1);
    int off_gs  = total;
    int off_gin = total + nseq;
    int off_ge  = off_gin + n_keep;
    int off_cd  = off_ge + nseq;

    // D first (independent; tiny)
    {
        int blocks = (ncol + 7) / 8;
        coldist_kernel<<<blocks, 256>>>(cols, W, b, out, ncol, dcol, off_cd);
    }
    // A: soft_argmax (HBM roofline kernel)
    {
        int blocks = (total + 7) / 8;       // 8 warps per 256-thread block
        soft_argmax_kernel<<<blocks, 256>>>(M, out, total, ncol, inv_ncol);
    }
    // BC: fused cumsum + boundary gaps + interior gaps
    {
        int blocks = (total - 1 + 511) / 512;
        bc_kernel<<<blocks, 512>>>(sl, out, nseq, total, ncolf, inv_ncol,
                                   off_gs, off_gin, off_ge);
    }
}

// round 4
// speedup vs baseline: 1.4150x; 1.0921x over previous
#include <cuda_runtime.h>
#include <cuda_bf16.h>
#include <math.h>

// ---------------------------------------------------------------------------
// SecDecoder outputs (flattened, concatenated in tuple order)
//   rp        [total]     = (M @ arange(ncol)) / ncol
//   gaps_start[nseq]      = sa[start_row]/ncol
//   gaps_in   [n_keep]    = (sa[g+1]-sa[g]-1)/ncol, g not a seq boundary
//   gaps_end  [nseq]      = (ncol - sa[end_row] - 1)/ncol
//   col_dist  [ncol*nout] = softmax(columns @ W + b)
// ---------------------------------------------------------------------------

#define MAX_TOTAL 131072
#define NOUT      26     // fixed by problem
#define JS        448    // j-range of W kept in smem (448*27*4 = 48384 B < 48KB)
#define KMAX      16     // dcol/32 (dcol = 512)

__device__ float g_sa[MAX_TOTAL];   // soft_argmax scratch

// Dtype-agnostic sequence_lengths accessor (harness may pass int64 or int32).
// Lengths are strictly positive; little-endian int64 => word[1]==0.
__device__ __forceinline__ bool sl_is_int64(const void* sl) {
    return ((const int*)sl)[1] == 0;
}
__device__ __forceinline__ long long sl_get(const void* sl, bool is64, int i) {
    if (is64) return ((const long long*)sl)[i];
    return (long long)((const int*)sl)[i];
}

// ---------------------------------------------------------------------------
// Kernel A: soft_argmax, one warp per row (8 float4 per lane).
// Measured ~7.1 TB/s — at the HBM roofline. Do not disturb.
// ---------------------------------------------------------------------------
__global__ void __launch_bounds__(256) soft_argmax_kernel(
    const float* __restrict__ M, float* __restrict__ out_rp,
    int total, int ncol, float inv_ncol)
{
    int warp = (blockIdx.x * blockDim.x + threadIdx.x) >> 5;
    int lane = threadIdx.x & 31;
    if (warp >= total) return;

    const float4* row = reinterpret_cast<const float4*>(M) + (size_t)warp * (ncol >> 2);
    float sum = 0.f;
    int nvec = ncol >> 2;
#pragma unroll 8
    for (int k = lane; k < nvec; k += 32) {
        float4 v = __ldg(row + k);
        float c = (float)(k << 2);
        sum = fmaf(v.x, c,        sum);
        sum = fmaf(v.y, c + 1.0f, sum);
        sum = fmaf(v.z, c + 2.0f, sum);
        sum = fmaf(v.w, c + 3.0f, sum);
    }
#pragma unroll
    for (int o = 16; o; o >>= 1)
        sum += __shfl_down_sync(0xffffffffu, sum, o);

    if (lane == 0) {
        g_sa[warp]   = sum;
        out_rp[warp] = sum * inv_ncol;
    }
}

// ---------------------------------------------------------------------------
// Kernel BC: fused boundaries + interior gaps. Every block redundantly scans
// the 500 sequence lengths in smem; block 0 additionally writes
// gaps_start / gaps_end. Interior gaps use a binary search over the in-smem
// cumsum for the removal test + compaction index.
// ---------------------------------------------------------------------------
__global__ void __launch_bounds__(512) bc_kernel(
    const void* __restrict__ sl, float* __restrict__ out,
    int nseq, int total, float ncolf, float inv_ncol,
    int off_gs, int off_gin, int off_ge)
{
    __shared__ long long s[512];
    int t = threadIdx.x;
    bool is64 = sl_is_int64(sl);
    s[t] = (t < nseq) ? sl_get(sl, is64, t) : 0;
    __syncthreads();

    for (int d = 1; d < nseq; d <<= 1) {
        long long v = (t >= d) ? s[t - d] : 0;
        __syncthreads();
        s[t] += v;
        __syncthreads();
    }

    if (blockIdx.x == 0 && t < nseq) {
        long long cs_t = s[t];
        long long row0 = (t == 0) ? 0 : s[t - 1];
        long long rowe = cs_t - 1;
        if (row0 < 0) row0 = 0; if (row0 >= total) row0 = total - 1;
        if (rowe < 0) rowe = 0; if (rowe >= total) rowe = total - 1;
        out[off_gs + t] = g_sa[row0] * inv_ncol;
        out[off_ge + t] = (ncolf - g_sa[rowe] - 1.0f) * inv_ncol;
    }

    int g = blockIdx.x * blockDim.x + t;
    if (g >= total - 1) return;

    int lo = 0, hi = nseq - 1;
    while (lo < hi) {
        int mid = (lo + hi) >> 1;
        if (s[mid] <= (long long)g) lo = mid + 1; else hi = mid;
    }
    int cnt = lo;
    bool removed = (cnt < nseq - 1) && (s[cnt] == (long long)g + 1);
    if (!removed) {
        float gap = g_sa[g + 1] - g_sa[g] - 1.0f;
        out[off_gin + (g - cnt)] = gap * inv_ncol;
    }
}

// ---------------------------------------------------------------------------
// Kernel D: col_dist = softmax(columns @ W + b).
// Warp per row; ALL 16 x-values prefetched into registers up front (MLP=16,
// one DRAM latency instead of a serialized chain). Main loop is pure
// LDS(stride-27, conflict-free) + FMA into 26 register accumulators.
// Tail (j >= JS) reads W straight from L2/L1. Butterfly reduce + warp softmax.
// ---------------------------------------------------------------------------
__global__ void __launch_bounds__(256) coldist_kernel(
    const float* __restrict__ columns, const float* __restrict__ W,
    const float* __restrict__ b, float* __restrict__ out,
    int ncol, int dcol, int off_cd)
{
    __shared__ float Ws[JS * 27];   // 48384 bytes

    int tid  = threadIdx.x;
    int warp = tid >> 5;
    int lane = tid & 31;

    int r = blockIdx.x * 8 + warp;

    // ---- prefetch x: 16 independent LDGs issued before anything else ----
    float x[KMAX];
    if (r < ncol) {
        const float* crow = columns + (size_t)r * dcol;
#pragma unroll
        for (int k = 0; k < KMAX; k++)
            x[k] = __ldg(crow + (k << 5) + lane);
    }

    // ---- cooperative W fill: warp strides j, lane = class (no div/mod) ----
    // LDG: 26 consecutive floats per (warp,j) — 1-2 lines; STS conflict-free.
    for (int j = warp; j < JS; j += 8) {
        if (lane < NOUT)
            Ws[j * 27 + lane] = __ldg(W + (size_t)j * NOUT + lane);
    }
    __syncthreads();

    if (r >= ncol) return;

    float acc[NOUT];
#pragma unroll
    for (int o = 0; o < NOUT; o++) acc[o] = 0.f;

    // smem region: j = k*32+lane < JS for k < JS/32 = 14
#pragma unroll
    for (int k = 0; k < JS / 32; k++) {
        const float* wrow = &Ws[((k << 5) + lane) * 27];
        float xv = x[k];
#pragma unroll
        for (int o = 0; o < NOUT; o++)
            acc[o] = fmaf(xv, wrow[o], acc[o]);
    }
    // global tail: k = 14, 15
#pragma unroll
    for (int k = JS / 32; k < KMAX; k++) {
        const float* wrow = W + (size_t)((k << 5) + lane) * NOUT;
        float xv = x[k];
#pragma unroll
        for (int o = 0; o < NOUT; o++)
            acc[o] = fmaf(xv, __ldg(wrow + o), acc[o]);
    }

    // butterfly-reduce each accumulator across the warp
#pragma unroll
    for (int o = 0; o < NOUT; o++) {
#pragma unroll
        for (int sft = 16; sft; sft >>= 1)
            acc[o] += __shfl_xor_sync(0xffffffffu, acc[o], sft);
    }

    // lane o takes logit o (+ bias); softmax across lanes
    float val = -INFINITY;
#pragma unroll
    for (int o = 0; o < NOUT; o++)
        if (lane == o) val = acc[o];
    bool active = (lane < NOUT);
    if (active) val += __ldg(b + lane);
    else        val  = -INFINITY;

    float m = val;
#pragma unroll
    for (int sft = 16; sft; sft >>= 1)
        m = fmaxf(m, __shfl_xor_sync(0xffffffffu, m, sft));
    float e = active ? expf(val - m) : 0.f;
    float sum = e;
#pragma unroll
    for (int sft = 16; sft; sft >>= 1)
        sum += __shfl_xor_sync(0xffffffffu, sum, sft);

    if (active) out[off_cd + (size_t)r * NOUT + lane] = e / sum;
}

// ---------------------------------------------------------------------------
extern "C" void kernel_launch(void* const* d_in, const int* in_sizes, int n_in,
                              void* d_out, int out_size)
{
    const float* M    = (const float*)d_in[0];
    const float* cols = (const float*)d_in[1];
    const void*  sl   = d_in[2];            // int32 or int64, probed on device
    const float* W    = (const float*)d_in[3];
    const float* b    = (const float*)d_in[4];
    float*       out  = (float*)d_out;

    int nout  = in_sizes[4];                // 26
    int dcol  = in_sizes[3] / nout;         // 512
    int ncol  = in_sizes[1] / dcol;         // 1024
    int total = in_sizes[0] / ncol;         // 100000
    int nseq  = in_sizes[2];                // 500

    float ncolf    = (float)ncol;
    float inv_ncol = 1.0f / ncolf;

    int n_keep  = (total - 1) - (nseq - 1);
    int off_gs  = total;
    int off_gin = total + nseq;
    int off_ge  = off_gin + n_keep;
    int off_cd  = off_ge + nseq;

    // D first (independent; tiny)
    {
        int blocks = (ncol + 7) / 8;
        coldist_kernel<<<blocks, 256>>>(cols, W, b, out, ncol, dcol, off_cd);
    }
    // A: soft_argmax (HBM roofline kernel)
    {
        int blocks = (total + 7) / 8;       // 8 warps per 256-thread block
        soft_argmax_kernel<<<blocks, 256>>>(M, out, total, ncol, inv_ncol);
    }
    // BC: fused cumsum + boundary gaps + interior gaps
    {
        int blocks = (total - 1 + 511) / 512;
        bc_kernel<<<blocks, 512>>>(sl, out, nseq, total, ncolf, inv_ncol,
                                   off_gs, off_gin, off_ge);
    }
}

// round 5
// speedup vs baseline: 1.6258x; 1.1489x over previous
#include <cuda_runtime.h>
#include <cuda_bf16.h>
#include <math.h>

// ---------------------------------------------------------------------------
// SecDecoder outputs (flattened, concatenated in tuple order)
//   rp        [total]     = (M @ arange(ncol)) / ncol
//   gaps_start[nseq]      = sa[start_row]/ncol
//   gaps_in   [n_keep]    = (sa[g+1]-sa[g]-1)/ncol, g not a seq boundary
//   gaps_end  [nseq]      = (ncol - sa[end_row] - 1)/ncol
//   col_dist  [ncol*nout] = softmax(columns @ W + b)
// ---------------------------------------------------------------------------

#define MAX_TOTAL 131072
#define NOUT      26     // fixed by problem
#define JS        448    // j-range of W kept in smem (448*27*4 = 48384 B)
#define KMAX      16     // dcol/32 (dcol = 512)
#define DBLOCKS   128    // coldist blocks (ncol/8)

__device__ float g_sa[MAX_TOTAL];   // soft_argmax scratch

// Dtype-agnostic sequence_lengths accessor (harness may pass int64 or int32).
// Lengths are strictly positive; little-endian int64 => word[1]==0.
__device__ __forceinline__ bool sl_is_int64(const void* sl) {
    return ((const int*)sl)[1] == 0;
}
__device__ __forceinline__ long long sl_get(const void* sl, bool is64, int i) {
    if (is64) return ((const long long*)sl)[i];
    return (long long)((const int*)sl)[i];
}

// ---------------------------------------------------------------------------
// Fused kernel AD:
//   blocks [0, DBLOCKS)        : col_dist = softmax(columns @ W + b)
//                                (latency-bound; hides under the A stream)
//   blocks [DBLOCKS, ...)      : soft_argmax rows (HBM roofline stream)
// D blocks are scheduled first so they overlap A's first waves.
// Static smem 48 KB caps occupancy at 4 blocks/SM = 32 warps — still enough
// MLP to saturate HBM for the A stream.
// ---------------------------------------------------------------------------
__global__ void __launch_bounds__(256) ad_kernel(
    const float* __restrict__ M, float* __restrict__ out,
    const float* __restrict__ columns, const float* __restrict__ W,
    const float* __restrict__ b,
    int total, int ncol, int dcol, float inv_ncol, int off_cd)
{
    __shared__ float Ws[JS * 27];   // 48384 bytes (D blocks only)

    int tid  = threadIdx.x;
    int warp = tid >> 5;
    int lane = tid & 31;

    if (blockIdx.x >= DBLOCKS) {
        // ------------------ A: soft_argmax, one warp per row ------------------
        int row_i = (blockIdx.x - DBLOCKS) * 8 + warp;
        if (row_i >= total) return;

        const float4* row = reinterpret_cast<const float4*>(M)
                          + (size_t)row_i * (ncol >> 2);
        float sum = 0.f;
        int nvec = ncol >> 2;
#pragma unroll 8
        for (int k = lane; k < nvec; k += 32) {
            float4 v = __ldg(row + k);
            float c = (float)(k << 2);
            sum = fmaf(v.x, c,        sum);
            sum = fmaf(v.y, c + 1.0f, sum);
            sum = fmaf(v.z, c + 2.0f, sum);
            sum = fmaf(v.w, c + 3.0f, sum);
        }
#pragma unroll
        for (int o = 16; o; o >>= 1)
            sum += __shfl_down_sync(0xffffffffu, sum, o);

        if (lane == 0) {
            g_sa[row_i] = sum;
            out[row_i]  = sum * inv_ncol;
        }
        return;
    }

    // ------------------ D: col_dist, one warp per column-row ------------------
    int r = blockIdx.x * 8 + warp;   // < 1024 always (128*8)

    // prefetch x: 16 independent LDGs before the fill loop
    float x[KMAX];
    {
        const float* crow = columns + (size_t)r * dcol;
#pragma unroll
        for (int k = 0; k < KMAX; k++)
            x[k] = __ldg(crow + (k << 5) + lane);
    }

    // cooperative W fill: warp strides j, lane = class (no div/mod)
    for (int j = warp; j < JS; j += 8) {
        if (lane < NOUT)
            Ws[j * 27 + lane] = __ldg(W + (size_t)j * NOUT + lane);
    }
    __syncthreads();

    float acc[NOUT];
#pragma unroll
    for (int o = 0; o < NOUT; o++) acc[o] = 0.f;

    // smem region: j = k*32+lane < JS for k < JS/32 = 14
#pragma unroll
    for (int k = 0; k < JS / 32; k++) {
        const float* wrow = &Ws[((k << 5) + lane) * 27];
        float xv = x[k];
#pragma unroll
        for (int o = 0; o < NOUT; o++)
            acc[o] = fmaf(xv, wrow[o], acc[o]);
    }
    // global tail: k = 14, 15 (W stays L1/L2-resident)
#pragma unroll
    for (int k = JS / 32; k < KMAX; k++) {
        const float* wrow = W + (size_t)((k << 5) + lane) * NOUT;
        float xv = x[k];
#pragma unroll
        for (int o = 0; o < NOUT; o++)
            acc[o] = fmaf(xv, __ldg(wrow + o), acc[o]);
    }

    // butterfly-reduce each accumulator across the warp
#pragma unroll
    for (int o = 0; o < NOUT; o++) {
#pragma unroll
        for (int sft = 16; sft; sft >>= 1)
            acc[o] += __shfl_xor_sync(0xffffffffu, acc[o], sft);
    }

    // lane o takes logit o (+ bias); softmax across lanes
    float val = -INFINITY;
#pragma unroll
    for (int o = 0; o < NOUT; o++)
        if (lane == o) val = acc[o];
    bool active = (lane < NOUT);
    if (active) val += __ldg(b + lane);
    else        val  = -INFINITY;

    float m = val;
#pragma unroll
    for (int sft = 16; sft; sft >>= 1)
        m = fmaxf(m, __shfl_xor_sync(0xffffffffu, m, sft));
    float e = active ? expf(val - m) : 0.f;
    float sum = e;
#pragma unroll
    for (int sft = 16; sft; sft >>= 1)
        sum += __shfl_xor_sync(0xffffffffu, sum, sft);

    if (active) out[off_cd + (size_t)r * NOUT + lane] = e / sum;
}

// ---------------------------------------------------------------------------
// Kernel BC: fused boundaries + interior gaps (needs g_sa complete, so it
// stays a second launch). Every block redundantly scans the sequence lengths
// in smem; block 0 additionally writes gaps_start / gaps_end.
// ---------------------------------------------------------------------------
__global__ void __launch_bounds__(512) bc_kernel(
    const void* __restrict__ sl, float* __restrict__ out,
    int nseq, int total, float ncolf, float inv_ncol,
    int off_gs, int off_gin, int off_ge)
{
    __shared__ long long s[512];
    int t = threadIdx.x;
    bool is64 = sl_is_int64(sl);
    s[t] = (t < nseq) ? sl_get(sl, is64, t) : 0;
    __syncthreads();

    for (int d = 1; d < nseq; d <<= 1) {
        long long v = (t >= d) ? s[t - d] : 0;
        __syncthreads();
        s[t] += v;
        __syncthreads();
    }

    if (blockIdx.x == 0 && t < nseq) {
        long long cs_t = s[t];
        long long row0 = (t == 0) ? 0 : s[t - 1];
        long long rowe = cs_t - 1;
        if (row0 < 0) row0 = 0; if (row0 >= total) row0 = total - 1;
        if (rowe < 0) rowe = 0; if (rowe >= total) rowe = total - 1;
        out[off_gs + t] = g_sa[row0] * inv_ncol;
        out[off_ge + t] = (ncolf - g_sa[rowe] - 1.0f) * inv_ncol;
    }

    int g = blockIdx.x * blockDim.x + t;
    if (g >= total - 1) return;

    int lo = 0, hi = nseq - 1;
    while (lo < hi) {
        int mid = (lo + hi) >> 1;
        if (s[mid] <= (long long)g) lo = mid + 1; else hi = mid;
    }
    int cnt = lo;
    bool removed = (cnt < nseq - 1) && (s[cnt] == (long long)g + 1);
    if (!removed) {
        float gap = g_sa[g + 1] - g_sa[g] - 1.0f;
        out[off_gin + (g - cnt)] = gap * inv_ncol;
    }
}

// ---------------------------------------------------------------------------
extern "C" void kernel_launch(void* const* d_in, const int* in_sizes, int n_in,
                              void* d_out, int out_size)
{
    const float* M    = (const float*)d_in[0];
    const float* cols = (const float*)d_in[1];
    const void*  sl   = d_in[2];            // int32 or int64, probed on device
    const float* W    = (const float*)d_in[3];
    const float* b    = (const float*)d_in[4];
    float*       out  = (float*)d_out;

    int nout  = in_sizes[4];                // 26
    int dcol  = in_sizes[3] / nout;         // 512
    int ncol  = in_sizes[1] / dcol;         // 1024
    int total = in_sizes[0] / ncol;         // 100000
    int nseq  = in_sizes[2];                // 500

    float ncolf    = (float)ncol;
    float inv_ncol = 1.0f / ncolf;

    int n_keep  = (total - 1) - (nseq - 1);
    int off_gs  = total;
    int off_gin = total + nseq;
    int off_ge  = off_gin + n_keep;
    int off_cd  = off_ge + nseq;

    // AD: fused soft_argmax stream + col_dist head
    {
        int a_blocks = (total + 7) / 8;     // 12500
        ad_kernel<<<DBLOCKS + a_blocks, 256>>>(
            M, out, cols, W, b, total, ncol, dcol, inv_ncol, off_cd);
    }
    // BC: fused cumsum + boundary gaps + interior gaps
    {
        int blocks = (total - 1 + 511) / 512;
        bc_kernel<<<blocks, 512>>>(sl, out, nseq, total, ncolf, inv_ncol,
                                   off_gs, off_gin, off_ge);
    }
}

// round 6
// speedup vs baseline: 1.6544x; 1.0176x over previous
#include <cuda_runtime.h>
#include <cuda_bf16.h>
#include <math.h>

// ---------------------------------------------------------------------------
// SecDecoder outputs (flattened, concatenated in tuple order)
//   rp        [total]     = (M @ arange(ncol)) / ncol
//   gaps_start[nseq]      = sa[start_row]/ncol
//   gaps_in   [n_keep]    = (sa[g+1]-sa[g]-1)/ncol, g not a seq boundary
//   gaps_end  [nseq]      = (ncol - sa[end_row] - 1)/ncol
//   col_dist  [ncol*nout] = softmax(columns @ W + b)
// ---------------------------------------------------------------------------

#define MAX_TOTAL 131072
#define MAX_NSEQ  1024
#define NOUT      26     // fixed by problem
#define KMAX      16     // dcol/32 (dcol = 512)
#define DBLOCKS   128    // coldist blocks (ncol/8)
#define ABASE     (1 + DBLOCKS)   // first A block index

__device__ float     g_sa[MAX_TOTAL];  // soft_argmax scratch
__device__ long long g_cs[MAX_NSEQ];   // cumsum(sequence_lengths)

// Dtype-agnostic sequence_lengths accessor (harness may pass int64 or int32).
// Lengths are strictly positive; little-endian int64 => word[1]==0.
__device__ __forceinline__ bool sl_is_int64(const void* sl) {
    return ((const int*)sl)[1] == 0;
}
__device__ __forceinline__ long long sl_get(const void* sl, bool is64, int i) {
    if (is64) return ((const long long*)sl)[i];
    return (long long)((const int*)sl)[i];
}

// ---------------------------------------------------------------------------
// Fused kernel AD (no static smem -> A runs at full 64-warp/SM occupancy):
//   block 0                  : cumsum(sequence_lengths) -> g_cs (warp scan;
//                              runs concurrently with A, effectively free)
//   blocks [1, 1+DBLOCKS)    : col_dist = softmax(columns @ W + b), W via
//                              L1/L2 (latency-bound, hidden under A)
//   blocks [ABASE, ...)      : soft_argmax rows (HBM roofline stream)
// ---------------------------------------------------------------------------
__global__ void __launch_bounds__(256) ad_kernel(
    const float* __restrict__ M, float* __restrict__ out,
    const float* __restrict__ columns, const float* __restrict__ W,
    const float* __restrict__ b, const void* __restrict__ sl,
    int total, int ncol, int dcol, int nseq, float inv_ncol, int off_cd)
{
    int tid  = threadIdx.x;
    int warp = tid >> 5;
    int lane = tid & 31;

    if (blockIdx.x >= ABASE) {
        // ---------------- A: soft_argmax, one warp per row ----------------
        int row_i = (blockIdx.x - ABASE) * 8 + warp;
        if (row_i >= total) return;

        const float4* row = reinterpret_cast<const float4*>(M)
                          + (size_t)row_i * (ncol >> 2);
        float sum = 0.f;
        int nvec = ncol >> 2;
#pragma unroll 8
        for (int k = lane; k < nvec; k += 32) {
            float4 v = __ldg(row + k);
            float c = (float)(k << 2);
            sum = fmaf(v.x, c,        sum);
            sum = fmaf(v.y, c + 1.0f, sum);
            sum = fmaf(v.z, c + 2.0f, sum);
            sum = fmaf(v.w, c + 3.0f, sum);
        }
#pragma unroll
        for (int o = 16; o; o >>= 1)
            sum += __shfl_down_sync(0xffffffffu, sum, o);

        if (lane == 0) {
            g_sa[row_i] = sum;
            out[row_i]  = sum * inv_ncol;
        }
        return;
    }

    if (blockIdx.x == 0) {
        // ---------------- cumsum via warp shuffle-scan (warp 0) ----------------
        if (warp == 0) {
            bool is64 = sl_is_int64(sl);
            long long carry = 0;
            int nchunks = (nseq + 31) >> 5;
            for (int c = 0; c < nchunks; c++) {
                int i = (c << 5) + lane;
                long long v = (i < nseq) ? sl_get(sl, is64, i) : 0;
#pragma unroll
                for (int s = 1; s < 32; s <<= 1) {
                    long long u = __shfl_up_sync(0xffffffffu, v, s);
                    if (lane >= s) v += u;
                }
                v += carry;
                if (i < nseq) g_cs[i] = v;
                carry = __shfl_sync(0xffffffffu, v, 31);
            }
        }
        return;
    }

    // ---------------- D: col_dist, one warp per column-row ----------------
    int r = (blockIdx.x - 1) * 8 + warp;   // < 1024 always

    // prefetch x: 16 independent LDGs up front (one DRAM latency)
    float x[KMAX];
    {
        const float* crow = columns + (size_t)r * dcol;
#pragma unroll
        for (int k = 0; k < KMAX; k++)
            x[k] = __ldg(crow + (k << 5) + lane);
    }

    float acc[NOUT];
#pragma unroll
    for (int o = 0; o < NOUT; o++) acc[o] = 0.f;

    // W read through L1/L2 (53 KB, resident after warm-up; hidden under A)
#pragma unroll
    for (int k = 0; k < KMAX; k++) {
        const float* wrow = W + (size_t)((k << 5) + lane) * NOUT;
        float xv = x[k];
#pragma unroll
        for (int o = 0; o < NOUT; o++)
            acc[o] = fmaf(xv, __ldg(wrow + o), acc[o]);
    }

    // butterfly-reduce each accumulator across the warp
#pragma unroll
    for (int o = 0; o < NOUT; o++) {
#pragma unroll
        for (int sft = 16; sft; sft >>= 1)
            acc[o] += __shfl_xor_sync(0xffffffffu, acc[o], sft);
    }

    // lane o takes logit o (+ bias); softmax across lanes
    float val = -INFINITY;
#pragma unroll
    for (int o = 0; o < NOUT; o++)
        if (lane == o) val = acc[o];
    bool active = (lane < NOUT);
    if (active) val += __ldg(b + lane);
    else        val  = -INFINITY;

    float m = val;
#pragma unroll
    for (int sft = 16; sft; sft >>= 1)
        m = fmaxf(m, __shfl_xor_sync(0xffffffffu, m, sft));
    float e = active ? expf(val - m) : 0.f;
    float sum = e;
#pragma unroll
    for (int sft = 16; sft; sft >>= 1)
        sum += __shfl_xor_sync(0xffffffffu, sum, sft);

    if (active) out[off_cd + (size_t)r * NOUT + lane] = e / sum;
}

// ---------------------------------------------------------------------------
// Kernel BC: boundary + interior gaps. Cumsum is precomputed in g_cs, so
// each block only coalesced-loads it into smem (one sync), then does a
// binary search for the removal test + compaction index.
// ---------------------------------------------------------------------------
__global__ void __launch_bounds__(512) bc_kernel(
    float* __restrict__ out,
    int nseq, int total, float ncolf, float inv_ncol,
    int off_gs, int off_gin, int off_ge)
{
    __shared__ long long s[MAX_NSEQ];
    int t = threadIdx.x;
    for (int i = t; i < nseq; i += blockDim.x) s[i] = g_cs[i];
    __syncthreads();

    if (blockIdx.x == 0 && t < nseq) {
        long long cs_t = s[t];
        long long row0 = (t == 0) ? 0 : s[t - 1];
        long long rowe = cs_t - 1;
        if (row0 < 0) row0 = 0; if (row0 >= total) row0 = total - 1;
        if (rowe < 0) rowe = 0; if (rowe >= total) rowe = total - 1;
        out[off_gs + t] = g_sa[row0] * inv_ncol;
        out[off_ge + t] = (ncolf - g_sa[rowe] - 1.0f) * inv_ncol;
    }

    int g = blockIdx.x * blockDim.x + t;
    if (g >= total - 1) return;

    // count of k in [0, nseq-2] with cs[k] <= g
    int lo = 0, hi = nseq - 1;
    while (lo < hi) {
        int mid = (lo + hi) >> 1;
        if (s[mid] <= (long long)g) lo = mid + 1; else hi = mid;
    }
    int cnt = lo;
    bool removed = (cnt < nseq - 1) && (s[cnt] == (long long)g + 1);
    if (!removed) {
        float gap = g_sa[g + 1] - g_sa[g] - 1.0f;
        out[off_gin + (g - cnt)] = gap * inv_ncol;
    }
}

// ---------------------------------------------------------------------------
extern "C" void kernel_launch(void* const* d_in, const int* in_sizes, int n_in,
                              void* d_out, int out_size)
{
    const float* M    = (const float*)d_in[0];
    const float* cols = (const float*)d_in[1];
    const void*  sl   = d_in[2];            // int32 or int64, probed on device
    const float* W    = (const float*)d_in[3];
    const float* b    = (const float*)d_in[4];
    float*       out  = (float*)d_out;

    int nout  = in_sizes[4];                // 26
    int dcol  = in_sizes[3] / nout;         // 512
    int ncol  = in_sizes[1] / dcol;         // 1024
    int total = in_sizes[0] / ncol;         // 100000
    int nseq  = in_sizes[2];                // 500

    float ncolf    = (float)ncol;
    float inv_ncol = 1.0f / ncolf;

    int n_keep  = (total - 1) - (nseq - 1);
    int off_gs  = total;
    int off_gin = total + nseq;
    int off_ge  = off_gin + n_keep;
    int off_cd  = off_ge + nseq;

    // AD: fused cumsum + col_dist + soft_argmax stream
    {
        int a_blocks = (total + 7) / 8;     // 12500
        ad_kernel<<<ABASE + a_blocks, 256>>>(
            M, out, cols, W, b, sl, total, ncol, dcol, nseq, inv_ncol, off_cd);
    }
    // BC: boundary + interior gaps (cumsum already in g_cs)
    {
        int blocks = (total - 1 + 511) / 512;
        bc_kernel<<<blocks, 512>>>(out, nseq, total, ncolf, inv_ncol,
                                   off_gs, off_gin, off_ge);
    }
}

// round 7
// speedup vs baseline: 1.7031x; 1.0294x over previous
#include <cuda_runtime.h>
#include <cuda_bf16.h>
#include <math.h>

// ---------------------------------------------------------------------------
// SecDecoder outputs (flattened, concatenated in tuple order)
//   rp        [total]     = (M @ arange(ncol)) / ncol
//   gaps_start[nseq]      = sa[start_row]/ncol
//   gaps_in   [n_keep]    = (sa[g+1]-sa[g]-1)/ncol, g not a seq boundary
//   gaps_end  [nseq]      = (ncol - sa[end_row] - 1)/ncol
//   col_dist  [ncol*nout] = softmax(columns @ W + b)
// ---------------------------------------------------------------------------

#define MAX_TOTAL 131072
#define MAX_NSEQ  1024
#define NOUT      26     // fixed by problem
#define KMAX      16     // dcol/32 (dcol = 512)
#define DBLOCKS   128    // coldist blocks (ncol/8)
#define ABASE     (1 + DBLOCKS)   // first A block index

__device__ float g_sa[MAX_TOTAL];  // soft_argmax scratch
__device__ int   g_cs[MAX_NSEQ];   // cumsum(sequence_lengths), fits int32

// Dtype-agnostic sequence_lengths accessor (harness may pass int64 or int32).
// Lengths are strictly positive; little-endian int64 => word[1]==0.
__device__ __forceinline__ bool sl_is_int64(const void* sl) {
    return ((const int*)sl)[1] == 0;
}
__device__ __forceinline__ int sl_get(const void* sl, bool is64, int i) {
    if (is64) return (int)((const long long*)sl)[i];
    return ((const int*)sl)[i];
}

// ---------------------------------------------------------------------------
// Fused kernel AD (no static smem -> A runs at full 64-warp/SM occupancy):
//   block 0                  : cumsum(sequence_lengths) -> g_cs (warp scan)
//   blocks [1, 1+DBLOCKS)    : col_dist = softmax(columns @ W + b)
//   blocks [ABASE, ...)      : soft_argmax rows (HBM roofline stream)
// ---------------------------------------------------------------------------
__global__ void __launch_bounds__(256) ad_kernel(
    const float* __restrict__ M, float* __restrict__ out,
    const float* __restrict__ columns, const float* __restrict__ W,
    const float* __restrict__ b, const void* __restrict__ sl,
    int total, int ncol, int dcol, int nseq, float inv_ncol, int off_cd)
{
    int tid  = threadIdx.x;
    int warp = tid >> 5;
    int lane = tid & 31;

    if (blockIdx.x >= ABASE) {
        // ---------------- A: soft_argmax, one warp per row ----------------
        int row_i = (blockIdx.x - ABASE) * 8 + warp;
        if (row_i >= total) return;

        const float4* row = reinterpret_cast<const float4*>(M)
                          + (size_t)row_i * (ncol >> 2);
        float sum = 0.f;
        int nvec = ncol >> 2;
#pragma unroll 8
        for (int k = lane; k < nvec; k += 32) {
            float4 v = __ldcs(row + k);        // read-once: evict-first
            float c = (float)(k << 2);
            sum = fmaf(v.x, c,        sum);
            sum = fmaf(v.y, c + 1.0f, sum);
            sum = fmaf(v.z, c + 2.0f, sum);
            sum = fmaf(v.w, c + 3.0f, sum);
        }
#pragma unroll
        for (int o = 16; o; o >>= 1)
            sum += __shfl_down_sync(0xffffffffu, sum, o);

        if (lane == 0) {
            g_sa[row_i] = sum;
            out[row_i]  = sum * inv_ncol;
        }
        return;
    }

    if (blockIdx.x == 0) {
        // ------------- cumsum via warp shuffle-scan (warp 0 only) -------------
        if (warp == 0) {
            bool is64 = sl_is_int64(sl);
            int carry = 0;
            int nchunks = (nseq + 31) >> 5;
            for (int c = 0; c < nchunks; c++) {
                int i = (c << 5) + lane;
                int v = (i < nseq) ? sl_get(sl, is64, i) : 0;
#pragma unroll
                for (int s = 1; s < 32; s <<= 1) {
                    int u = __shfl_up_sync(0xffffffffu, v, s);
                    if (lane >= s) v += u;
                }
                v += carry;
                if (i < nseq) g_cs[i] = v;
                carry = __shfl_sync(0xffffffffu, v, 31);
            }
        }
        return;
    }

    // ---------------- D: col_dist, one warp per column-row ----------------
    int r = (blockIdx.x - 1) * 8 + warp;   // < 1024 always

    // prefetch x: 16 independent LDGs up front (one DRAM latency)
    float x[KMAX];
    {
        const float* crow = columns + (size_t)r * dcol;
#pragma unroll
        for (int k = 0; k < KMAX; k++)
            x[k] = __ldg(crow + (k << 5) + lane);
    }

    float acc[NOUT];
#pragma unroll
    for (int o = 0; o < NOUT; o++) acc[o] = 0.f;

    // W read through L1/L2 (53 KB, resident after warm-up; hidden under A)
#pragma unroll
    for (int k = 0; k < KMAX; k++) {
        const float* wrow = W + (size_t)((k << 5) + lane) * NOUT;
        float xv = x[k];
#pragma unroll
        for (int o = 0; o < NOUT; o++)
            acc[o] = fmaf(xv, __ldg(wrow + o), acc[o]);
    }

    // butterfly-reduce each accumulator across the warp
#pragma unroll
    for (int o = 0; o < NOUT; o++) {
#pragma unroll
        for (int sft = 16; sft; sft >>= 1)
            acc[o] += __shfl_xor_sync(0xffffffffu, acc[o], sft);
    }

    // lane o takes logit o (+ bias); softmax across lanes
    float val = -INFINITY;
#pragma unroll
    for (int o = 0; o < NOUT; o++)
        if (lane == o) val = acc[o];
    bool active = (lane < NOUT);
    if (active) val += __ldg(b + lane);
    else        val  = -INFINITY;

    float m = val;
#pragma unroll
    for (int sft = 16; sft; sft >>= 1)
        m = fmaxf(m, __shfl_xor_sync(0xffffffffu, m, sft));
    float e = active ? expf(val - m) : 0.f;
    float sum = e;
#pragma unroll
    for (int sft = 16; sft; sft >>= 1)
        sum += __shfl_xor_sync(0xffffffffu, sum, sft);

    if (active) out[off_cd + (size_t)r * NOUT + lane] = e / sum;
}

// ---------------------------------------------------------------------------
// Kernel BC: boundary + interior gaps. Cumsum precomputed in g_cs (int32).
// 256-thread blocks: finer wave spread; each block coalesced-loads cs into
// smem once, binary-searches for the removal test + compaction index.
// Boundary outputs distributed by global thread id.
// ---------------------------------------------------------------------------
__global__ void __launch_bounds__(256) bc_kernel(
    float* __restrict__ out,
    int nseq, int total, float ncolf, float inv_ncol,
    int off_gs, int off_gin, int off_ge)
{
    __shared__ int s[MAX_NSEQ];
    int t = threadIdx.x;
    for (int i = t; i < nseq; i += 256) s[i] = __ldg(&g_cs[i]);
    __syncthreads();

    int gt = blockIdx.x * 256 + t;

    if (gt < nseq) {
        int cs_t = s[gt];
        int row0 = (gt == 0) ? 0 : s[gt - 1];
        out[off_gs + gt] = __ldg(&g_sa[row0]) * inv_ncol;
        out[off_ge + gt] = (ncolf - __ldg(&g_sa[cs_t - 1]) - 1.0f) * inv_ncol;
    }

    if (gt >= total - 1) return;

    // count of k in [0, nseq-2] with cs[k] <= gt
    int lo = 0, hi = nseq - 1;
    while (lo < hi) {
        int mid = (lo + hi) >> 1;
        if (s[mid] <= gt) lo = mid + 1; else hi = mid;
    }
    int cnt = lo;
    bool removed = (cnt < nseq - 1) && (s[cnt] == gt + 1);
    if (!removed) {
        float gap = __ldg(&g_sa[gt + 1]) - __ldg(&g_sa[gt]) - 1.0f;
        out[off_gin + (gt - cnt)] = gap * inv_ncol;
    }
}

// ---------------------------------------------------------------------------
extern "C" void kernel_launch(void* const* d_in, const int* in_sizes, int n_in,
                              void* d_out, int out_size)
{
    const float* M    = (const float*)d_in[0];
    const float* cols = (const float*)d_in[1];
    const void*  sl   = d_in[2];            // int32 or int64, probed on device
    const float* W    = (const float*)d_in[3];
    const float* b    = (const float*)d_in[4];
    float*       out  = (float*)d_out;

    int nout  = in_sizes[4];                // 26
    int dcol  = in_sizes[3] / nout;         // 512
    int ncol  = in_sizes[1] / dcol;         // 1024
    int total = in_sizes[0] / ncol;         // 100000
    int nseq  = in_sizes[2];                // 500

    float ncolf    = (float)ncol;
    float inv_ncol = 1.0f / ncolf;

    int n_keep  = (total - 1) - (nseq - 1);
    int off_gs  = total;
    int off_gin = total + nseq;
    int off_ge  = off_gin + n_keep;
    int off_cd  = off_ge + nseq;

    // AD: fused cumsum + col_dist + soft_argmax stream
    {
        int a_blocks = (total + 7) / 8;     // 12500
        ad_kernel<<<ABASE + a_blocks, 256>>>(
            M, out, cols, W, b, sl, total, ncol, dcol, nseq, inv_ncol, off_cd);
    }
    // BC: boundary + interior gaps (cumsum already in g_cs)
    {
        int blocks = (total - 1 + 255) / 256;
        bc_kernel<<<blocks, 256>>>(out, nseq, total, ncolf, inv_ncol,
                                   off_gs, off_gin, off_ge);
    }
}

// round 8
// speedup vs baseline: 1.7099x; 1.0039x over previous
#include <cuda_runtime.h>
#include <cuda_bf16.h>
#include <math.h>

// ---------------------------------------------------------------------------
// SecDecoder outputs (flattened, concatenated in tuple order)
//   rp        [total]     = (M @ arange(ncol)) / ncol
//   gaps_start[nseq]      = sa[start_row]/ncol
//   gaps_in   [n_keep]    = (sa[g+1]-sa[g]-1)/ncol, g not a seq boundary
//   gaps_end  [nseq]      = (ncol - sa[end_row] - 1)/ncol
//   col_dist  [ncol*nout] = softmax(columns @ W + b)
// ---------------------------------------------------------------------------

#define MAX_TOTAL 131072
#define MAX_NSEQ  1024
#define NOUT      26     // fixed by problem
#define KMAX      16     // dcol/32 (dcol = 512)
#define DBLOCKS   128    // coldist blocks (ncol/8)
#define ABASE     (1 + DBLOCKS)   // first A block index

__device__ float g_sa[MAX_TOTAL];  // soft_argmax scratch
__device__ int   g_cs[MAX_NSEQ];   // cumsum(sequence_lengths), fits int32
__device__ int   g_uniL;           // uniform length if all equal, else 0

// Dtype-agnostic sequence_lengths accessor (harness may pass int64 or int32).
// Lengths are strictly positive; little-endian int64 => word[1]==0.
__device__ __forceinline__ bool sl_is_int64(const void* sl) {
    return ((const int*)sl)[1] == 0;
}
__device__ __forceinline__ int sl_get(const void* sl, bool is64, int i) {
    if (is64) return (int)((const long long*)sl)[i];
    return ((const int*)sl)[i];
}

// ---------------------------------------------------------------------------
// Fused kernel AD (no static smem -> A runs at full occupancy):
//   block 0                  : cumsum(sequence_lengths) -> g_cs (warp scan)
//                              + uniform-length detection -> g_uniL
//   blocks [1, 1+DBLOCKS)    : col_dist = softmax(columns @ W + b)
//   blocks [ABASE, ...)      : soft_argmax rows (HBM roofline stream)
// ---------------------------------------------------------------------------
__global__ void __launch_bounds__(256) ad_kernel(
    const float* __restrict__ M, float* __restrict__ out,
    const float* __restrict__ columns, const float* __restrict__ W,
    const float* __restrict__ b, const void* __restrict__ sl,
    int total, int ncol, int dcol, int nseq, float inv_ncol, int off_cd)
{
    int tid  = threadIdx.x;
    int warp = tid >> 5;
    int lane = tid & 31;

    if (blockIdx.x >= ABASE) {
        // ---------------- A: soft_argmax, one warp per row ----------------
        int row_i = (blockIdx.x - ABASE) * 8 + warp;
        if (row_i >= total) return;

        const float4* row = reinterpret_cast<const float4*>(M)
                          + (size_t)row_i * (ncol >> 2);
        float sum = 0.f;
        int nvec = ncol >> 2;
#pragma unroll 8
        for (int k = lane; k < nvec; k += 32) {
            float4 v = __ldcs(row + k);        // read-once: evict-first
            float c = (float)(k << 2);
            sum = fmaf(v.x, c,        sum);
            sum = fmaf(v.y, c + 1.0f, sum);
            sum = fmaf(v.z, c + 2.0f, sum);
            sum = fmaf(v.w, c + 3.0f, sum);
        }
#pragma unroll
        for (int o = 16; o; o >>= 1)
            sum += __shfl_down_sync(0xffffffffu, sum, o);

        if (lane == 0) {
            g_sa[row_i] = sum;
            out[row_i]  = sum * inv_ncol;
        }
        return;
    }

    if (blockIdx.x == 0) {
        // ------- cumsum via warp shuffle-scan + uniformity detection -------
        if (warp == 0) {
            bool is64 = sl_is_int64(sl);
            int L0 = sl_get(sl, is64, 0);
            int carry = 0;
            bool uni = true;
            int nchunks = (nseq + 31) >> 5;
            for (int c = 0; c < nchunks; c++) {
                int i = (c << 5) + lane;
                int v = (i < nseq) ? sl_get(sl, is64, i) : 0;
                if (i < nseq && v != L0) uni = false;
#pragma unroll
                for (int s = 1; s < 32; s <<= 1) {
                    int u = __shfl_up_sync(0xffffffffu, v, s);
                    if (lane >= s) v += u;
                }
                v += carry;
                if (i < nseq) g_cs[i] = v;
                carry = __shfl_sync(0xffffffffu, v, 31);
            }
            bool all_uni = __all_sync(0xffffffffu, uni);
            if (lane == 0) g_uniL = all_uni ? L0 : 0;
        }
        return;
    }

    // ---------------- D: col_dist, one warp per column-row ----------------
    int r = (blockIdx.x - 1) * 8 + warp;   // < 1024 always

    // prefetch x: 16 independent LDGs up front (one DRAM latency)
    float x[KMAX];
    {
        const float* crow = columns + (size_t)r * dcol;
#pragma unroll
        for (int k = 0; k < KMAX; k++)
            x[k] = __ldg(crow + (k << 5) + lane);
    }

    float acc[NOUT];
#pragma unroll
    for (int o = 0; o < NOUT; o++) acc[o] = 0.f;

    // W read through L1/L2 (53 KB, resident after warm-up; hidden under A)
#pragma unroll
    for (int k = 0; k < KMAX; k++) {
        const float* wrow = W + (size_t)((k << 5) + lane) * NOUT;
        float xv = x[k];
#pragma unroll
        for (int o = 0; o < NOUT; o++)
            acc[o] = fmaf(xv, __ldg(wrow + o), acc[o]);
    }

    // butterfly-reduce each accumulator across the warp
#pragma unroll
    for (int o = 0; o < NOUT; o++) {
#pragma unroll
        for (int sft = 16; sft; sft >>= 1)
            acc[o] += __shfl_xor_sync(0xffffffffu, acc[o], sft);
    }

    // lane o takes logit o (+ bias); softmax across lanes
    float val = -INFINITY;
#pragma unroll
    for (int o = 0; o < NOUT; o++)
        if (lane == o) val = acc[o];
    bool active = (lane < NOUT);
    if (active) val += __ldg(b + lane);
    else        val  = -INFINITY;

    float m = val;
#pragma unroll
    for (int sft = 16; sft; sft >>= 1)
        m = fmaxf(m, __shfl_xor_sync(0xffffffffu, m, sft));
    float e = active ? expf(val - m) : 0.f;
    float sum = e;
#pragma unroll
    for (int sft = 16; sft; sft >>= 1)
        sum += __shfl_xor_sync(0xffffffffu, sum, sft);

    if (active) out[off_cd + (size_t)r * NOUT + lane] = e / sum;
}

// ---------------------------------------------------------------------------
// Kernel BC: boundary + interior gaps.
// Uniform-length fast path (no smem, no sync, no search): cnt = gt / L,
// removed iff (cnt+1)*L == gt+1, boundary rows by multiplication.
// Fallback (non-uniform): binary search over g_cs straight from L2.
// ---------------------------------------------------------------------------
__global__ void __launch_bounds__(256) bc_kernel(
    float* __restrict__ out,
    int nseq, int total, float ncolf, float inv_ncol,
    int off_gs, int off_gin, int off_ge)
{
    int gt = blockIdx.x * 256 + threadIdx.x;
    int L  = g_uniL;   // broadcast load

    if (L > 0) {
        // ------------------------- uniform fast path -------------------------
        if (gt < nseq) {
            int row0 = gt * L;
            int rowe = row0 + L - 1;
            out[off_gs + gt] = __ldg(&g_sa[row0]) * inv_ncol;
            out[off_ge + gt] = (ncolf - __ldg(&g_sa[rowe]) - 1.0f) * inv_ncol;
        }
        if (gt >= total - 1) return;

        int cnt = gt / L;
        if (cnt > nseq - 1) cnt = nseq - 1;
        bool removed = (cnt < nseq - 1) && ((cnt + 1) * L == gt + 1);
        if (!removed) {
            float gap = __ldg(&g_sa[gt + 1]) - __ldg(&g_sa[gt]) - 1.0f;
            out[off_gin + (gt - cnt)] = gap * inv_ncol;
        }
        return;
    }

    // --------------------- general path (non-uniform) ---------------------
    if (gt < nseq) {
        int cs_t = __ldg(&g_cs[gt]);
        int row0 = (gt == 0) ? 0 : __ldg(&g_cs[gt - 1]);
        out[off_gs + gt] = __ldg(&g_sa[row0]) * inv_ncol;
        out[off_ge + gt] = (ncolf - __ldg(&g_sa[cs_t - 1]) - 1.0f) * inv_ncol;
    }
    if (gt >= total - 1) return;

    int lo = 0, hi = nseq - 1;
    while (lo < hi) {
        int mid = (lo + hi) >> 1;
        if (__ldg(&g_cs[mid]) <= gt) lo = mid + 1; else hi = mid;
    }
    int cnt = lo;
    bool removed = (cnt < nseq - 1) && (__ldg(&g_cs[cnt]) == gt + 1);
    if (!removed) {
        float gap = __ldg(&g_sa[gt + 1]) - __ldg(&g_sa[gt]) - 1.0f;
        out[off_gin + (gt - cnt)] = gap * inv_ncol;
    }
}

// ---------------------------------------------------------------------------
extern "C" void kernel_launch(void* const* d_in, const int* in_sizes, int n_in,
                              void* d_out, int out_size)
{
    const float* M    = (const float*)d_in[0];
    const float* cols = (const float*)d_in[1];
    const void*  sl   = d_in[2];            // int32 or int64, probed on device
    const float* W    = (const float*)d_in[3];
    const float* b    = (const float*)d_in[4];
    float*       out  = (float*)d_out;

    int nout  = in_sizes[4];                // 26
    int dcol  = in_sizes[3] / nout;         // 512
    int ncol  = in_sizes[1] / dcol;         // 1024
    int total = in_sizes[0] / ncol;         // 100000
    int nseq  = in_sizes[2];                // 500

    float ncolf    = (float)ncol;
    float inv_ncol = 1.0f / ncolf;

    int n_keep  = (total - 1) - (nseq - 1);
    int off_gs  = total;
    int off_gin = total + nseq;
    int off_ge  = off_gin + n_keep;
    int off_cd  = off_ge + nseq;

    // AD: fused cumsum/uniformity + col_dist + soft_argmax stream
    {
        int a_blocks = (total + 7) / 8;     // 12500
        ad_kernel<<<ABASE + a_blocks, 256>>>(
            M, out, cols, W, b, sl, total, ncol, dcol, nseq, inv_ncol, off_cd);
    }
    // BC: boundary + interior gaps
    {
        int blocks = (total - 1 + 255) / 256;
        bc_kernel<<<blocks, 256>>>(out, nseq, total, ncolf, inv_ncol,
                                   off_gs, off_gin, off_ge);
    }
}